// round 12
// baseline (speedup 1.0000x reference)
#include <cuda_runtime.h>
#include <cuda_bf16.h>

// Problem constants
#define NB   2
#define NPTS 8192
#define NS   1024
#define NK   16
#define NC   29

// Output layout (concatenated flattened reference returns, float32):
// new_xyz  (2,3,1024)    -> [0, 6144)
// new_points (2,128,1024)-> [6144, 268288)
// fps_idx  (2,1024)      -> [268288, 270336)
#define OUT_NP  6144
#define OUT_FPS 268288

// Scratch (static device globals; no allocation allowed)
__device__ int   g_fps[NB * NS];
__device__ float g_newxyz[NB * 3 * NS];
__device__ int   g_knn[NB * NS * NK];

// ---- packed f32x2 helpers (Blackwell; PTX-only, per-lane IEEE fp32) ----
__device__ __forceinline__ unsigned long long pk2(float lo, float hi)
{
    unsigned long long r;
    asm("mov.b64 %0, {%1,%2};" : "=l"(r) : "f"(lo), "f"(hi));
    return r;
}
__device__ __forceinline__ unsigned long long fma2(unsigned long long a,
                                                   unsigned long long b,
                                                   unsigned long long c)
{
    unsigned long long d;
    asm("fma.rn.f32x2 %0, %1, %2, %3;" : "=l"(d) : "l"(a), "l"(b), "l"(c));
    return d;
}
__device__ __forceinline__ unsigned long long add2(unsigned long long a,
                                                   unsigned long long b)
{
    unsigned long long d;
    asm("add.rn.f32x2 %0, %1, %2;" : "=l"(d) : "l"(a), "l"(b));
    return d;
}
__device__ __forceinline__ unsigned long long mul2(unsigned long long a,
                                                   unsigned long long b)
{
    unsigned long long d;
    asm("mul.rn.f32x2 %0, %1, %2;" : "=l"(d) : "l"(a), "l"(b));
    return d;
}
__device__ __forceinline__ void upk2(unsigned long long v, float& lo, float& hi)
{
    asm("mov.b64 {%0,%1}, %2;" : "=f"(lo), "=f"(hi) : "l"(v));
}

// ---------------------------------------------------------------------------
// Kernel 1: FPS. One CTA/batch, 1024 threads, 8 pts/thread. Distances via
// packed f32x2 (per-lane identical to scalar __fsub/__fmul/__fadd_rn chain:
// a+(-b) == a-b exactly). Argmax: scalar fmax tree (dists >= 0 so float max
// == bit max), REDUX on dist bits, rare predicated idx scan (first-occurrence
// via max of 8191-idx), REDUX on idx-key; two-stage with parity-buffered
// leader slots and ONE barrier per iteration.
// ---------------------------------------------------------------------------
__global__ void __launch_bounds__(1024) fps_kernel(const float* __restrict__ xyz,
                                                   float* __restrict__ out)
{
    const int b    = blockIdx.x;
    const int tid  = threadIdx.x;
    const int lane = tid & 31;
    const int warp = tid >> 5;
    const float* X = xyz + b * 3 * NPTS;

    // pair j holds points p=2j (lo lane) and p=2j+1 (hi lane)
    unsigned long long pxp[4], pyp[4], pzp[4];
    float dd[8];
#pragma unroll
    for (int j = 0; j < 4; j++) {
        int n0 = tid + (2 * j) * 1024;
        int n1 = tid + (2 * j + 1) * 1024;
        pxp[j] = pk2(X[n0], X[n1]);
        pyp[j] = pk2(X[NPTS + n0], X[NPTS + n1]);
        pzp[j] = pk2(X[2 * NPTS + n0], X[2 * NPTS + n1]);
        dd[2 * j] = 1e10f; dd[2 * j + 1] = 1e10f;
    }

    __shared__ unsigned long long wmax[2][32];

    int f = 0;
    for (int s = 0; s < NS; s++) {
        float cx = X[f];
        float cy = X[NPTS + f];
        float cz = X[2 * NPTS + f];

        if (tid == 0) {
            g_fps[b * NS + s] = f;
            out[OUT_FPS + b * NS + s] = (float)f;
            g_newxyz[b * 3072 + s]        = cx;
            g_newxyz[b * 3072 + 1024 + s] = cy;
            g_newxyz[b * 3072 + 2048 + s] = cz;
            out[b * 3072 + s]        = cx;
            out[b * 3072 + 1024 + s] = cy;
            out[b * 3072 + 2048 + s] = cz;
        }

        const unsigned long long c2x = pk2(-cx, -cx);
        const unsigned long long c2y = pk2(-cy, -cy);
        const unsigned long long c2z = pk2(-cz, -cz);

#pragma unroll
        for (int j = 0; j < 4; j++) {
            unsigned long long dx = add2(pxp[j], c2x);
            unsigned long long dy = add2(pyp[j], c2y);
            unsigned long long dz = add2(pzp[j], c2z);
            unsigned long long t  = add2(mul2(dx, dx), mul2(dy, dy));
            unsigned long long d  = add2(t, mul2(dz, dz));
            float d0, d1;
            upk2(d, d0, d1);
            dd[2 * j]     = fminf(dd[2 * j], d0);
            dd[2 * j + 1] = fminf(dd[2 * j + 1], d1);
        }

        // thread max (dists >= 0: float max == bit max)
        float m01 = fmaxf(dd[0], dd[1]), m23 = fmaxf(dd[2], dd[3]);
        float m45 = fmaxf(dd[4], dd[5]), m67 = fmaxf(dd[6], dd[7]);
        float m   = fmaxf(fmaxf(m01, m23), fmaxf(m45, m67));

        unsigned mb  = __float_as_uint(m);
        unsigned whi = __reduce_max_sync(0xffffffffu, mb);
        unsigned idxkey = 0;
        if (mb == whi) {
#pragma unroll
            for (int p = 0; p < 8; p++)
                if (__float_as_uint(dd[p]) == whi) {
                    unsigned k = (unsigned)(8191 - (tid + p * 1024));
                    idxkey = (k > idxkey) ? k : idxkey;
                }
        }
        unsigned wlo = __reduce_max_sync(0xffffffffu, idxkey);
        if (lane == 0)
            wmax[s & 1][warp] = ((unsigned long long)whi << 32) | wlo;
        __syncthreads();

        // every warp reduces the 32 leader keys -> uniform f
        unsigned long long v = wmax[s & 1][lane];
        unsigned h2 = (unsigned)(v >> 32);
        unsigned l2 = (unsigned)v;
        unsigned fh = __reduce_max_sync(0xffffffffu, h2);
        unsigned fl = __reduce_max_sync(0xffffffffu, (h2 == fh) ? l2 : 0u);
        f = 8191 - (int)fl;
    }
}

// ---------------------------------------------------------------------------
// Kernel 2: KNN among the 1024 sampled points. Numerics (validated R6):
//   sq  : non-contracted mul/add chain (XLA fusion)
//   dot : cublas FFMA chain fma(z, z, fma(y, y, x*x))
//   d2  : (sq_i + sq_j) - 2*dot, non-contracted.
// ---------------------------------------------------------------------------
__global__ void __launch_bounds__(128) knn_kernel()
{
    __shared__ float snx[3072];
    const int b = blockIdx.x >> 3;                    // 16 blocks: 8 per batch
    const int s = (blockIdx.x & 7) * 128 + threadIdx.x;

    for (int t = threadIdx.x; t < 3072; t += 128)
        snx[t] = g_newxyz[b * 3072 + t];
    __syncthreads();

    const float xi = snx[s], yi = snx[1024 + s], zi = snx[2048 + s];
    const float sqi = __fadd_rn(__fadd_rn(__fmul_rn(xi, xi), __fmul_rn(yi, yi)),
                                __fmul_rn(zi, zi));

    float bd[16];
    int   bi[16];
#pragma unroll
    for (int k = 0; k < 16; k++) { bd[k] = 3.4e38f; bi[k] = 0; }

    for (int j = 0; j < NS; j++) {
        float xj = snx[j], yj = snx[1024 + j], zj = snx[2048 + j];
        float sqj = __fadd_rn(__fadd_rn(__fmul_rn(xj, xj), __fmul_rn(yj, yj)),
                              __fmul_rn(zj, zj));
        float dot = __fmaf_rn(zi, zj, __fmaf_rn(yi, yj, __fmul_rn(xi, xj)));
        float d2  = __fsub_rn(__fadd_rn(sqi, sqj), __fmul_rn(2.0f, dot));
        if (d2 < bd[15]) {
            int p = 15;
            while (p > 0 && bd[p - 1] > d2) {
                bd[p] = bd[p - 1];
                bi[p] = bi[p - 1];
                p--;
            }
            bd[p] = d2;
            bi[p] = j;
        }
    }

    const int base = (b * NS + s) * NK;
    for (int k = 0; k < 16; k++) g_knn[base + k] = bi[k];
}

// ---------------------------------------------------------------------------
// Kernel 3: fused build + conv0..conv3 + relu, one CTA per sample.
// KEY CHANGE vs R8: og = lane, oy = warp -> all 32 lanes of a warp read the
// SAME activation row address (broadcast, conflict-free) instead of
// lane-varying rows (3KB/warp crossbar + 2-way conflicts). Weight pairs
// staged [icc][k][og] -> lane-stride-1 LDS.64, conflict-free. conv3 weights
// staged [k][tid] (was 4-way conflicted). Arithmetic identical -> bit-exact.
//
// Shared layout (floats):
//   fg 512 | x0 16384 | ws 4608 | y0 2304 | y1 1024 | y2 512 = 25344
// ---------------------------------------------------------------------------
#define SMEM_FLOATS 25344

__global__ void __launch_bounds__(192) fused_conv_kernel(
    const float* __restrict__ feats,
    const float* __restrict__ w0, const float* __restrict__ w1,
    const float* __restrict__ w2, const float* __restrict__ w3,
    float* __restrict__ out)
{
    extern __shared__ float sm[];
    float* fg = sm;             // 512
    float* x0 = sm + 512;       // 16384
    float* ws = x0 + 16384;     // 4608   (8B-aligned: offset 16896 floats)
    float* y0 = ws + 4608;      // 2304
    float* y1 = y0 + 2304;      // 1024
    float* y2 = y1 + 1024;      // 512
    unsigned long long* ws2 = reinterpret_cast<unsigned long long*>(ws);

    const int sid = blockIdx.x;
    const int b   = sid >> 10;
    const int s   = sid & 1023;
    const int tid = threadIdx.x;

    // --- Phase A: fg[d][k] ---------------------------------------------
    for (int t = tid; t < 512; t += 192) {
        int d = t >> 4, k = t & 15;
        int j = g_knn[sid * NK + k];
        float v;
        if (d < 3)
            v = g_newxyz[b * 3072 + d * 1024 + j] - g_newxyz[b * 3072 + d * 1024 + s];
        else
            v = feats[(b * NC + (d - 3)) * NPTS + j];
        fg[t] = v;
    }
    __syncthreads();

    // --- Phase B: build squeezed conv0 input ----------------------------
    for (int t = tid; t < 16384; t += 192) {
        int oc = t >> 6, pix = t & 63;
        int y = pix >> 3, x = pix & 7;
        int q = oc >> 6, c = oc & 63;
        float v = 1.0f;
        if (c < 32) {
            int i = 2 * y + (int)(q == 1 || q == 3);
            int j = 2 * x + (int)(q == 1 || q == 2);
            v = fg[c * 16 + i] * fg[c * 16 + j];
        }
        x0[t] = v;
    }

    // --- conv0: 256ch 8x8 -> 64ch 6x6 (f32x2; og=lane, oy=warp) ----------
    const int og = tid & 31;   // lane: oc pair 2og, 2og+1
    const int oy = tid >> 5;   // warp: output row 0..5
    unsigned long long acc2[6];
#pragma unroll
    for (int i = 0; i < 6; i++) acc2[i] = 0ull;

    for (int ch = 0; ch < 32; ch++) {
        const int ic0 = ch * 8;
        __syncthreads();                 // protect ws from previous readers
        // stage pairs: ws2[icc*288 + k*32 + og] = (w0[2og][ic][k], w0[2og+1][ic][k])
        for (int t = tid; t < 2304; t += 192) {
            int icc = t / 288, rem = t % 288;
            int k = rem >> 5, ogs = rem & 31;
            int ic = ic0 + icc;
            float wa = w0[(2 * ogs)     * 2304 + ic * 9 + k];
            float wb = w0[(2 * ogs + 1) * 2304 + ic * 9 + k];
            ws2[t] = pk2(wa, wb);
        }
        __syncthreads();
        for (int icc = 0; icc < 8; icc++) {
            const float* xs = x0 + ((ic0 + icc) << 6);
            unsigned long long xp[3][8];
#pragma unroll
            for (int r = 0; r < 3; r++) {   // uniform address per warp -> broadcast
                const float4 v0 = *reinterpret_cast<const float4*>(xs + (oy + r) * 8);
                const float4 v1 = *reinterpret_cast<const float4*>(xs + (oy + r) * 8 + 4);
                xp[r][0] = pk2(v0.x, v0.x); xp[r][1] = pk2(v0.y, v0.y);
                xp[r][2] = pk2(v0.z, v0.z); xp[r][3] = pk2(v0.w, v0.w);
                xp[r][4] = pk2(v1.x, v1.x); xp[r][5] = pk2(v1.y, v1.y);
                xp[r][6] = pk2(v1.z, v1.z); xp[r][7] = pk2(v1.w, v1.w);
            }
            const unsigned long long* wp2 = ws2 + icc * 288 + og;
#pragma unroll
            for (int ky = 0; ky < 3; ky++)
#pragma unroll
                for (int kx = 0; kx < 3; kx++) {
                    unsigned long long wv = wp2[(ky * 3 + kx) * 32];
#pragma unroll
                    for (int ox = 0; ox < 6; ox++)
                        acc2[ox] = fma2(wv, xp[ky][ox + kx], acc2[ox]);
                }
        }
    }
    {
        int oc = og * 2;
#pragma unroll
        for (int ox = 0; ox < 6; ox++) {
            float a0, a1;
            upk2(acc2[ox], a0, a1);
            y0[oc * 36 + oy * 6 + ox]       = fmaxf(a0, 0.f);
            y0[(oc + 1) * 36 + oy * 6 + ox] = fmaxf(a1, 0.f);
        }
    }

    // --- conv1: 64ch 6x6 -> 64ch 4x4 (f32x2; og=lane, oy=warp) -----------
    const int og1 = tid & 31;
    const int oy1 = tid >> 5;  // warps 0..3 active (tid < 128)
    unsigned long long bcc[4];
#pragma unroll
    for (int i = 0; i < 4; i++) bcc[i] = 0ull;

    for (int ch = 0; ch < 8; ch++) {
        const int ic0 = ch * 8;
        __syncthreads();
        for (int t = tid; t < 2304; t += 192) {
            int icc = t / 288, rem = t % 288;
            int k = rem >> 5, ogs = rem & 31;
            int ic = ic0 + icc;
            float wa = w1[(2 * ogs)     * 576 + ic * 9 + k];
            float wb = w1[(2 * ogs + 1) * 576 + ic * 9 + k];
            ws2[t] = pk2(wa, wb);
        }
        __syncthreads();
        if (tid < 128) {
            for (int icc = 0; icc < 8; icc++) {
                const float* xs = y0 + (ic0 + icc) * 36;
                unsigned long long xp[3][6];
#pragma unroll
                for (int r = 0; r < 3; r++) {   // uniform per warp -> broadcast
                    const float2 v0 = *reinterpret_cast<const float2*>(xs + (oy1 + r) * 6);
                    const float2 v1 = *reinterpret_cast<const float2*>(xs + (oy1 + r) * 6 + 2);
                    const float2 v2 = *reinterpret_cast<const float2*>(xs + (oy1 + r) * 6 + 4);
                    xp[r][0] = pk2(v0.x, v0.x); xp[r][1] = pk2(v0.y, v0.y);
                    xp[r][2] = pk2(v1.x, v1.x); xp[r][3] = pk2(v1.y, v1.y);
                    xp[r][4] = pk2(v2.x, v2.x); xp[r][5] = pk2(v2.y, v2.y);
                }
                const unsigned long long* wp2 = ws2 + icc * 288 + og1;
#pragma unroll
                for (int ky = 0; ky < 3; ky++)
#pragma unroll
                    for (int kx = 0; kx < 3; kx++) {
                        unsigned long long wv = wp2[(ky * 3 + kx) * 32];
#pragma unroll
                        for (int ox = 0; ox < 4; ox++)
                            bcc[ox] = fma2(wv, xp[ky][ox + kx], bcc[ox]);
                    }
            }
        }
    }
    if (tid < 128) {
        int oc = og1 * 2;
#pragma unroll
        for (int ox = 0; ox < 4; ox++) {
            float b0, b1;
            upk2(bcc[ox], b0, b1);
            y1[oc * 16 + oy1 * 4 + ox]       = fmaxf(b0, 0.f);
            y1[(oc + 1) * 16 + oy1 * 4 + ox] = fmaxf(b1, 0.f);
        }
    }

    // --- conv2: 64ch 4x4 -> 128ch 2x2 (scalar; weights stride-9 = c.f.) --
    float c2[4] = {0.f, 0.f, 0.f, 0.f};
    for (int ch = 0; ch < 16; ch++) {
        const int ic0 = ch * 4;
        __syncthreads();
        for (int t = tid; t < 4608; t += 192) {
            int icc = t / 1152, rem = t % 1152;
            int oc = rem / 9, k = rem % 9;
            ws[t] = w2[oc * 576 + (ic0 + icc) * 9 + k];
        }
        __syncthreads();
        if (tid < 128) {
            for (int icc = 0; icc < 4; icc++) {
                const float* xs = y1 + (ic0 + icc) * 16;   // uniform -> broadcast
                float xr[16];
#pragma unroll
                for (int p = 0; p < 4; p++) {
                    const float4 v = *reinterpret_cast<const float4*>(xs + p * 4);
                    xr[p * 4 + 0] = v.x; xr[p * 4 + 1] = v.y;
                    xr[p * 4 + 2] = v.z; xr[p * 4 + 3] = v.w;
                }
                const float* wp = ws + icc * 1152 + tid * 9;  // stride 9: conflict-free
#pragma unroll
                for (int ky = 0; ky < 3; ky++)
#pragma unroll
                    for (int kx = 0; kx < 3; kx++) {
                        float wv = wp[ky * 3 + kx];
#pragma unroll
                        for (int oy2 = 0; oy2 < 2; oy2++)
#pragma unroll
                            for (int ox2 = 0; ox2 < 2; ox2++)
                                c2[oy2 * 2 + ox2] += xr[(oy2 + ky) * 4 + ox2 + kx] * wv;
                    }
            }
        }
    }
    if (tid < 128) {
#pragma unroll
        for (int p = 0; p < 4; p++) y2[tid * 4 + p] = fmaxf(c2[p], 0.f);
    }

    // --- conv3: 128ch 2x2 -> 128ch 1x1 (weights staged [k][tid]) ---------
    float acc3 = 0.f;
    for (int ch = 0; ch < 16; ch++) {
        const int ic0 = ch * 8;
        __syncthreads();
        for (int t = tid; t < 4096; t += 192) {
            int icc = t >> 9, rem = t & 511;
            int k = rem >> 7, oc = rem & 127;
            ws[t] = w3[oc * 512 + (ic0 + icc) * 4 + k];
        }
        __syncthreads();
        if (tid < 128) {
            for (int icc = 0; icc < 8; icc++) {
                const float* xs = y2 + (ic0 + icc) * 4;        // uniform
                const float* wp = ws + icc * 512 + tid;        // stride-1: c.f.
                acc3 += xs[0] * wp[0] + xs[1] * wp[128] + xs[2] * wp[256] + xs[3] * wp[384];
            }
        }
    }
    if (tid < 128) {
        out[OUT_NP + b * 131072 + tid * 1024 + s] = fmaxf(acc3, 0.f);
    }
}

// ---------------------------------------------------------------------------
extern "C" void kernel_launch(void* const* d_in, const int* in_sizes, int n_in,
                              void* d_out, int out_size)
{
    const float* xyz   = (const float*)d_in[0];
    const float* feats = (const float*)d_in[1];
    const float* w0    = (const float*)d_in[2];
    const float* w1    = (const float*)d_in[3];
    const float* w2    = (const float*)d_in[4];
    const float* w3    = (const float*)d_in[5];
    float* out = (float*)d_out;

    cudaFuncSetAttribute(fused_conv_kernel,
                         cudaFuncAttributeMaxDynamicSharedMemorySize,
                         SMEM_FLOATS * (int)sizeof(float));

    fps_kernel<<<NB, 1024>>>(xyz, out);
    knn_kernel<<<16, 128>>>();
    fused_conv_kernel<<<NB * NS, 192, SMEM_FLOATS * sizeof(float)>>>(
        feats, w0, w1, w2, w3, out);
}

// round 13
// speedup vs baseline: 1.5019x; 1.5019x over previous
#include <cuda_runtime.h>
#include <cuda_bf16.h>

// Problem constants
#define NB   2
#define NPTS 8192
#define NS   1024
#define NK   16
#define NC   29

// Output layout (concatenated flattened reference returns, float32):
// new_xyz  (2,3,1024)    -> [0, 6144)
// new_points (2,128,1024)-> [6144, 268288)
// fps_idx  (2,1024)      -> [268288, 270336)
#define OUT_NP  6144
#define OUT_FPS 268288

// Scratch (static device globals; no allocation allowed)
__device__ int   g_fps[NB * NS];
__device__ float g_newxyz[NB * 3 * NS];
__device__ int   g_knn[NB * NS * NK];

// ---- packed f32x2 helpers (Blackwell; PTX-only, per-lane IEEE fp32) ----
__device__ __forceinline__ unsigned long long pk2(float lo, float hi)
{
    unsigned long long r;
    asm("mov.b64 %0, {%1,%2};" : "=l"(r) : "f"(lo), "f"(hi));
    return r;
}
__device__ __forceinline__ unsigned long long fma2(unsigned long long a,
                                                   unsigned long long b,
                                                   unsigned long long c)
{
    unsigned long long d;
    asm("fma.rn.f32x2 %0, %1, %2, %3;" : "=l"(d) : "l"(a), "l"(b), "l"(c));
    return d;
}
__device__ __forceinline__ unsigned long long add2(unsigned long long a,
                                                   unsigned long long b)
{
    unsigned long long d;
    asm("add.rn.f32x2 %0, %1, %2;" : "=l"(d) : "l"(a), "l"(b));
    return d;
}
__device__ __forceinline__ unsigned long long mul2(unsigned long long a,
                                                   unsigned long long b)
{
    unsigned long long d;
    asm("mul.rn.f32x2 %0, %1, %2;" : "=l"(d) : "l"(a), "l"(b));
    return d;
}
__device__ __forceinline__ void upk2(unsigned long long v, float& lo, float& hi)
{
    asm("mov.b64 {%0,%1}, %2;" : "=f"(lo), "=f"(hi) : "l"(v));
}

// ---------------------------------------------------------------------------
// Kernel 1: FPS (R12 version, measured 627us). Packed f32x2 distance math
// (per-lane identical to the scalar non-contracted chain), scalar fmax tree,
// REDUX two-stage argmax, parity-buffered leader slots, one barrier/iter.
// ---------------------------------------------------------------------------
__global__ void __launch_bounds__(1024) fps_kernel(const float* __restrict__ xyz,
                                                   float* __restrict__ out)
{
    const int b    = blockIdx.x;
    const int tid  = threadIdx.x;
    const int lane = tid & 31;
    const int warp = tid >> 5;
    const float* X = xyz + b * 3 * NPTS;

    unsigned long long pxp[4], pyp[4], pzp[4];
    float dd[8];
#pragma unroll
    for (int j = 0; j < 4; j++) {
        int n0 = tid + (2 * j) * 1024;
        int n1 = tid + (2 * j + 1) * 1024;
        pxp[j] = pk2(X[n0], X[n1]);
        pyp[j] = pk2(X[NPTS + n0], X[NPTS + n1]);
        pzp[j] = pk2(X[2 * NPTS + n0], X[2 * NPTS + n1]);
        dd[2 * j] = 1e10f; dd[2 * j + 1] = 1e10f;
    }

    __shared__ unsigned long long wmax[2][32];

    int f = 0;
    for (int s = 0; s < NS; s++) {
        float cx = X[f];
        float cy = X[NPTS + f];
        float cz = X[2 * NPTS + f];

        if (tid == 0) {
            g_fps[b * NS + s] = f;
            out[OUT_FPS + b * NS + s] = (float)f;
            g_newxyz[b * 3072 + s]        = cx;
            g_newxyz[b * 3072 + 1024 + s] = cy;
            g_newxyz[b * 3072 + 2048 + s] = cz;
            out[b * 3072 + s]        = cx;
            out[b * 3072 + 1024 + s] = cy;
            out[b * 3072 + 2048 + s] = cz;
        }

        const unsigned long long c2x = pk2(-cx, -cx);
        const unsigned long long c2y = pk2(-cy, -cy);
        const unsigned long long c2z = pk2(-cz, -cz);

#pragma unroll
        for (int j = 0; j < 4; j++) {
            unsigned long long dx = add2(pxp[j], c2x);
            unsigned long long dy = add2(pyp[j], c2y);
            unsigned long long dz = add2(pzp[j], c2z);
            unsigned long long t  = add2(mul2(dx, dx), mul2(dy, dy));
            unsigned long long d  = add2(t, mul2(dz, dz));
            float d0, d1;
            upk2(d, d0, d1);
            dd[2 * j]     = fminf(dd[2 * j], d0);
            dd[2 * j + 1] = fminf(dd[2 * j + 1], d1);
        }

        float m01 = fmaxf(dd[0], dd[1]), m23 = fmaxf(dd[2], dd[3]);
        float m45 = fmaxf(dd[4], dd[5]), m67 = fmaxf(dd[6], dd[7]);
        float m   = fmaxf(fmaxf(m01, m23), fmaxf(m45, m67));

        unsigned mb  = __float_as_uint(m);
        unsigned whi = __reduce_max_sync(0xffffffffu, mb);
        unsigned idxkey = 0;
        if (mb == whi) {
#pragma unroll
            for (int p = 0; p < 8; p++)
                if (__float_as_uint(dd[p]) == whi) {
                    unsigned k = (unsigned)(8191 - (tid + p * 1024));
                    idxkey = (k > idxkey) ? k : idxkey;
                }
        }
        unsigned wlo = __reduce_max_sync(0xffffffffu, idxkey);
        if (lane == 0)
            wmax[s & 1][warp] = ((unsigned long long)whi << 32) | wlo;
        __syncthreads();

        unsigned long long v = wmax[s & 1][lane];
        unsigned h2 = (unsigned)(v >> 32);
        unsigned l2 = (unsigned)v;
        unsigned fh = __reduce_max_sync(0xffffffffu, h2);
        unsigned fl = __reduce_max_sync(0xffffffffu, (h2 == fh) ? l2 : 0u);
        f = 8191 - (int)fl;
    }
}

// ---------------------------------------------------------------------------
// Kernel 2: KNN (validated numerics, unchanged).
// ---------------------------------------------------------------------------
__global__ void __launch_bounds__(128) knn_kernel()
{
    __shared__ float snx[3072];
    const int b = blockIdx.x >> 3;                    // 16 blocks: 8 per batch
    const int s = (blockIdx.x & 7) * 128 + threadIdx.x;

    for (int t = threadIdx.x; t < 3072; t += 128)
        snx[t] = g_newxyz[b * 3072 + t];
    __syncthreads();

    const float xi = snx[s], yi = snx[1024 + s], zi = snx[2048 + s];
    const float sqi = __fadd_rn(__fadd_rn(__fmul_rn(xi, xi), __fmul_rn(yi, yi)),
                                __fmul_rn(zi, zi));

    float bd[16];
    int   bi[16];
#pragma unroll
    for (int k = 0; k < 16; k++) { bd[k] = 3.4e38f; bi[k] = 0; }

    for (int j = 0; j < NS; j++) {
        float xj = snx[j], yj = snx[1024 + j], zj = snx[2048 + j];
        float sqj = __fadd_rn(__fadd_rn(__fmul_rn(xj, xj), __fmul_rn(yj, yj)),
                              __fmul_rn(zj, zj));
        float dot = __fmaf_rn(zi, zj, __fmaf_rn(yi, yj, __fmul_rn(xi, xj)));
        float d2  = __fsub_rn(__fadd_rn(sqi, sqj), __fmul_rn(2.0f, dot));
        if (d2 < bd[15]) {
            int p = 15;
            while (p > 0 && bd[p - 1] > d2) {
                bd[p] = bd[p - 1];
                bi[p] = bi[p - 1];
                p--;
            }
            bd[p] = d2;
            bi[p] = j;
        }
    }

    const int base = (b * NS + s) * NK;
    for (int k = 0; k < 16; k++) g_knn[base + k] = bi[k];
}

// ---------------------------------------------------------------------------
// Kernel 3: fused conv — R11 structure (measured-good: coalesced weight
// staging with k fastest, og=tid/6 compute mapping) extended to TWO samples
// per CTA: 384 threads = two 192-thread teams, each owning one sample.
// Weights are staged ONCE per chunk by all 384 threads and consumed by both
// teams -> per-sample staging LDG volume, w0 L2 traffic and barrier count
// all halved. Arithmetic identical to R11 -> bit-exact output.
//
// Shared layout (floats):
//   ws 4608 | team0 {fg 512, x0 16384, y0 2304, y1 1024, y2 512} = 20736
//           | team1 {...} = 20736     -> total 46080 floats = 184320 B
// ---------------------------------------------------------------------------
#define TEAM_FLOATS 20736
#define SMEM_FLOATS (4608 + 2 * TEAM_FLOATS)

__global__ void __launch_bounds__(384) fused_conv_kernel(
    const float* __restrict__ feats,
    const float* __restrict__ w0, const float* __restrict__ w1,
    const float* __restrict__ w2, const float* __restrict__ w3,
    float* __restrict__ out)
{
    extern __shared__ float sm[];
    float* ws = sm;                                   // 4608 (8B aligned)
    unsigned long long* ws2 = reinterpret_cast<unsigned long long*>(ws);

    const int tid  = threadIdx.x;
    const int team = tid / 192;
    const int ttid = tid % 192;

    float* tb = sm + 4608 + team * TEAM_FLOATS;
    float* fg = tb;              // 512
    float* x0 = tb + 512;        // 16384
    float* y0 = tb + 16896;      // 2304
    float* y1 = y0 + 2304;       // 1024
    float* y2 = y1 + 1024;       // 512

    const int sid = blockIdx.x * 2 + team;
    const int b   = sid >> 10;
    const int s   = sid & 1023;

    // --- Phase A: fg[d][k] (per team) -----------------------------------
    for (int t = ttid; t < 512; t += 192) {
        int d = t >> 4, k = t & 15;
        int j = g_knn[sid * NK + k];
        float v;
        if (d < 3)
            v = g_newxyz[b * 3072 + d * 1024 + j] - g_newxyz[b * 3072 + d * 1024 + s];
        else
            v = feats[(b * NC + (d - 3)) * NPTS + j];
        fg[t] = v;
    }
    __syncthreads();

    // --- Phase B: build squeezed conv0 input (per team) ------------------
    for (int t = ttid; t < 16384; t += 192) {
        int oc = t >> 6, pix = t & 63;
        int y = pix >> 3, x = pix & 7;
        int q = oc >> 6, c = oc & 63;
        float v = 1.0f;
        if (c < 32) {
            int i = 2 * y + (int)(q == 1 || q == 3);
            int j = 2 * x + (int)(q == 1 || q == 2);
            v = fg[c * 16 + i] * fg[c * 16 + j];
        }
        x0[t] = v;
    }

    // --- conv0: 256ch 8x8 -> 64ch 6x6 (f32x2; R11 mapping) ---------------
    const int oy = ttid % 6;
    const int og = ttid / 6;   // 0..31, oc = 2*og, 2*og+1
    unsigned long long acc2[6];
#pragma unroll
    for (int i = 0; i < 6; i++) acc2[i] = 0ull;

    for (int ch = 0; ch < 32; ch++) {
        const int ic0 = ch * 8;
        __syncthreads();                 // protect ws from previous readers
        // R11 staging order (k fastest -> coalesced LDG), all 384 threads
        for (int t = tid; t < 2304; t += 384) {
            int k = t % 9, rest = t / 9;
            int ogs = rest % 32, icc = rest / 32;
            int ic  = ic0 + icc;
            float wa = w0[(2 * ogs)     * 2304 + ic * 9 + k];
            float wb = w0[(2 * ogs + 1) * 2304 + ic * 9 + k];
            ws2[t] = pk2(wa, wb);
        }
        __syncthreads();
        for (int icc = 0; icc < 8; icc++) {
            const float* xs = x0 + ((ic0 + icc) << 6);
            unsigned long long xp[3][8];
#pragma unroll
            for (int r = 0; r < 3; r++) {
                const float4 v0 = *reinterpret_cast<const float4*>(xs + (oy + r) * 8);
                const float4 v1 = *reinterpret_cast<const float4*>(xs + (oy + r) * 8 + 4);
                xp[r][0] = pk2(v0.x, v0.x); xp[r][1] = pk2(v0.y, v0.y);
                xp[r][2] = pk2(v0.z, v0.z); xp[r][3] = pk2(v0.w, v0.w);
                xp[r][4] = pk2(v1.x, v1.x); xp[r][5] = pk2(v1.y, v1.y);
                xp[r][6] = pk2(v1.z, v1.z); xp[r][7] = pk2(v1.w, v1.w);
            }
            const unsigned long long* wp2 = ws2 + (icc * 32 + og) * 9;
#pragma unroll
            for (int ky = 0; ky < 3; ky++)
#pragma unroll
                for (int kx = 0; kx < 3; kx++) {
                    unsigned long long wv = wp2[ky * 3 + kx];
#pragma unroll
                    for (int ox = 0; ox < 6; ox++)
                        acc2[ox] = fma2(wv, xp[ky][ox + kx], acc2[ox]);
                }
        }
    }
    {
        int oc = og * 2;
#pragma unroll
        for (int ox = 0; ox < 6; ox++) {
            float a0, a1;
            upk2(acc2[ox], a0, a1);
            y0[oc * 36 + oy * 6 + ox]       = fmaxf(a0, 0.f);
            y0[(oc + 1) * 36 + oy * 6 + ox] = fmaxf(a1, 0.f);
        }
    }

    // --- conv1: 64ch 6x6 -> 64ch 4x4 (f32x2; R11 mapping) ----------------
    const int oy1 = ttid % 4;
    const int og1 = ttid / 4;  // valid for ttid<128
    unsigned long long bcc[4];
#pragma unroll
    for (int i = 0; i < 4; i++) bcc[i] = 0ull;

    for (int ch = 0; ch < 8; ch++) {
        const int ic0 = ch * 8;
        __syncthreads();
        for (int t = tid; t < 2304; t += 384) {
            int k = t % 9, rest = t / 9;
            int ogs = rest % 32, icc = rest / 32;
            int ic  = ic0 + icc;
            float wa = w1[(2 * ogs)     * 576 + ic * 9 + k];
            float wb = w1[(2 * ogs + 1) * 576 + ic * 9 + k];
            ws2[t] = pk2(wa, wb);
        }
        __syncthreads();
        if (ttid < 128) {
            for (int icc = 0; icc < 8; icc++) {
                const float* xs = y0 + (ic0 + icc) * 36;
                unsigned long long xp[3][6];
#pragma unroll
                for (int r = 0; r < 3; r++) {
                    const float2 v0 = *reinterpret_cast<const float2*>(xs + (oy1 + r) * 6);
                    const float2 v1 = *reinterpret_cast<const float2*>(xs + (oy1 + r) * 6 + 2);
                    const float2 v2 = *reinterpret_cast<const float2*>(xs + (oy1 + r) * 6 + 4);
                    xp[r][0] = pk2(v0.x, v0.x); xp[r][1] = pk2(v0.y, v0.y);
                    xp[r][2] = pk2(v1.x, v1.x); xp[r][3] = pk2(v1.y, v1.y);
                    xp[r][4] = pk2(v2.x, v2.x); xp[r][5] = pk2(v2.y, v2.y);
                }
                const unsigned long long* wp2 = ws2 + (icc * 32 + og1) * 9;
#pragma unroll
                for (int ky = 0; ky < 3; ky++)
#pragma unroll
                    for (int kx = 0; kx < 3; kx++) {
                        unsigned long long wv = wp2[ky * 3 + kx];
#pragma unroll
                        for (int ox = 0; ox < 4; ox++)
                            bcc[ox] = fma2(wv, xp[ky][ox + kx], bcc[ox]);
                    }
            }
        }
    }
    if (ttid < 128) {
        int oc = og1 * 2;
#pragma unroll
        for (int ox = 0; ox < 4; ox++) {
            float b0, b1;
            upk2(bcc[ox], b0, b1);
            y1[oc * 16 + oy1 * 4 + ox]       = fmaxf(b0, 0.f);
            y1[(oc + 1) * 16 + oy1 * 4 + ox] = fmaxf(b1, 0.f);
        }
    }

    // --- conv2: 64ch 4x4 -> 128ch 2x2 (scalar; R11 staging) --------------
    float c2[4] = {0.f, 0.f, 0.f, 0.f};
    for (int ch = 0; ch < 16; ch++) {
        const int ic0 = ch * 4;
        __syncthreads();
        for (int t = tid; t < 4608; t += 384) {
            int icc = t / 1152, rem = t % 1152;
            int oc = rem / 9, k = rem % 9;
            ws[t] = w2[oc * 576 + (ic0 + icc) * 9 + k];
        }
        __syncthreads();
        if (ttid < 128) {
            for (int icc = 0; icc < 4; icc++) {
                const float* xs = y1 + (ic0 + icc) * 16;
                float xr[16];
#pragma unroll
                for (int p = 0; p < 4; p++) {
                    const float4 v = *reinterpret_cast<const float4*>(xs + p * 4);
                    xr[p * 4 + 0] = v.x; xr[p * 4 + 1] = v.y;
                    xr[p * 4 + 2] = v.z; xr[p * 4 + 3] = v.w;
                }
                const float* wp = ws + icc * 1152 + ttid * 9;
#pragma unroll
                for (int ky = 0; ky < 3; ky++)
#pragma unroll
                    for (int kx = 0; kx < 3; kx++) {
                        float wv = wp[ky * 3 + kx];
#pragma unroll
                        for (int oy2 = 0; oy2 < 2; oy2++)
#pragma unroll
                            for (int ox2 = 0; ox2 < 2; ox2++)
                                c2[oy2 * 2 + ox2] += xr[(oy2 + ky) * 4 + ox2 + kx] * wv;
                    }
            }
        }
    }
    if (ttid < 128) {
#pragma unroll
        for (int p = 0; p < 4; p++) y2[ttid * 4 + p] = fmaxf(c2[p], 0.f);
    }

    // --- conv3: 128ch 2x2 -> 128ch 1x1 (scalar; R11 staging) -------------
    float acc3 = 0.f;
    for (int ch = 0; ch < 16; ch++) {
        const int ic0 = ch * 8;
        __syncthreads();
        for (int t = tid; t < 4096; t += 384) {
            int icc = t >> 9, rem = t & 511;
            int oc = rem >> 2, k = rem & 3;
            ws[t] = w3[oc * 512 + (ic0 + icc) * 4 + k];
        }
        __syncthreads();
        if (ttid < 128) {
            for (int icc = 0; icc < 8; icc++) {
                const float* xs = y2 + (ic0 + icc) * 4;
                const float* wp = ws + icc * 512 + ttid * 4;
                acc3 += xs[0] * wp[0] + xs[1] * wp[1] + xs[2] * wp[2] + xs[3] * wp[3];
            }
        }
    }
    if (ttid < 128) {
        out[OUT_NP + b * 131072 + ttid * 1024 + s] = fmaxf(acc3, 0.f);
    }
}

// ---------------------------------------------------------------------------
extern "C" void kernel_launch(void* const* d_in, const int* in_sizes, int n_in,
                              void* d_out, int out_size)
{
    const float* xyz   = (const float*)d_in[0];
    const float* feats = (const float*)d_in[1];
    const float* w0    = (const float*)d_in[2];
    const float* w1    = (const float*)d_in[3];
    const float* w2    = (const float*)d_in[4];
    const float* w3    = (const float*)d_in[5];
    float* out = (float*)d_out;

    cudaFuncSetAttribute(fused_conv_kernel,
                         cudaFuncAttributeMaxDynamicSharedMemorySize,
                         SMEM_FLOATS * (int)sizeof(float));

    fps_kernel<<<NB, 1024>>>(xyz, out);
    knn_kernel<<<16, 128>>>();
    fused_conv_kernel<<<NB * NS / 2, 384, SMEM_FLOATS * sizeof(float)>>>(
        feats, w0, w1, w2, w3, out);
}

// round 14
// speedup vs baseline: 1.9469x; 1.2963x over previous
#include <cuda_runtime.h>
#include <cuda_bf16.h>

// Problem constants
#define NB   2
#define NPTS 8192
#define NS   1024
#define NK   16
#define NC   29

// Output layout (concatenated flattened reference returns, float32):
// new_xyz  (2,3,1024)    -> [0, 6144)
// new_points (2,128,1024)-> [6144, 268288)
// fps_idx  (2,1024)      -> [268288, 270336)
#define OUT_NP  6144
#define OUT_FPS 268288

// Scratch (static device globals; no allocation allowed)
__device__ int   g_fps[NB * NS];
__device__ float g_newxyz[NB * 3 * NS];
__device__ int   g_knn[NB * NS * NK];
__device__ float g_bias0[64];   // conv0 ones-channel contribution per oc

// ---- packed f32x2 helpers (Blackwell; PTX-only, per-lane IEEE fp32) ----
__device__ __forceinline__ unsigned long long pk2(float lo, float hi)
{
    unsigned long long r;
    asm("mov.b64 %0, {%1,%2};" : "=l"(r) : "f"(lo), "f"(hi));
    return r;
}
__device__ __forceinline__ unsigned long long fma2(unsigned long long a,
                                                   unsigned long long b,
                                                   unsigned long long c)
{
    unsigned long long d;
    asm("fma.rn.f32x2 %0, %1, %2, %3;" : "=l"(d) : "l"(a), "l"(b), "l"(c));
    return d;
}
__device__ __forceinline__ unsigned long long add2(unsigned long long a,
                                                   unsigned long long b)
{
    unsigned long long d;
    asm("add.rn.f32x2 %0, %1, %2;" : "=l"(d) : "l"(a), "l"(b));
    return d;
}
__device__ __forceinline__ unsigned long long mul2(unsigned long long a,
                                                   unsigned long long b)
{
    unsigned long long d;
    asm("mul.rn.f32x2 %0, %1, %2;" : "=l"(d) : "l"(a), "l"(b));
    return d;
}
__device__ __forceinline__ void upk2(unsigned long long v, float& lo, float& hi)
{
    asm("mov.b64 {%0,%1}, %2;" : "=f"(lo), "=f"(hi) : "l"(v));
}

// ---------------------------------------------------------------------------
// Kernel 0: precompute conv0 ones-channel bias.
// bias0[oc] = sum over q in 0..3, c in 32..63, tap k in 0..8 of
//             w0[oc][q*64+c][k].  Input-independent; fp32 sum (order noise
//             is in the same 1e-6 class as any accumulation-order change).
// ---------------------------------------------------------------------------
__global__ void bias0_kernel(const float* __restrict__ w0)
{
    int oc = threadIdx.x;       // 64 threads
    float s = 0.f;
    for (int q = 0; q < 4; q++)
        for (int c = 32; c < 64; c++) {
            const float* p = w0 + oc * 2304 + (q * 64 + c) * 9;
#pragma unroll
            for (int k = 0; k < 9; k++) s += p[k];
        }
    g_bias0[oc] = s;
}

// ---------------------------------------------------------------------------
// Kernel 1: FPS (R12/R13 version, measured 626us).
// ---------------------------------------------------------------------------
__global__ void __launch_bounds__(1024) fps_kernel(const float* __restrict__ xyz,
                                                   float* __restrict__ out)
{
    const int b    = blockIdx.x;
    const int tid  = threadIdx.x;
    const int lane = tid & 31;
    const int warp = tid >> 5;
    const float* X = xyz + b * 3 * NPTS;

    unsigned long long pxp[4], pyp[4], pzp[4];
    float dd[8];
#pragma unroll
    for (int j = 0; j < 4; j++) {
        int n0 = tid + (2 * j) * 1024;
        int n1 = tid + (2 * j + 1) * 1024;
        pxp[j] = pk2(X[n0], X[n1]);
        pyp[j] = pk2(X[NPTS + n0], X[NPTS + n1]);
        pzp[j] = pk2(X[2 * NPTS + n0], X[2 * NPTS + n1]);
        dd[2 * j] = 1e10f; dd[2 * j + 1] = 1e10f;
    }

    __shared__ unsigned long long wmax[2][32];

    int f = 0;
    for (int s = 0; s < NS; s++) {
        float cx = X[f];
        float cy = X[NPTS + f];
        float cz = X[2 * NPTS + f];

        if (tid == 0) {
            g_fps[b * NS + s] = f;
            out[OUT_FPS + b * NS + s] = (float)f;
            g_newxyz[b * 3072 + s]        = cx;
            g_newxyz[b * 3072 + 1024 + s] = cy;
            g_newxyz[b * 3072 + 2048 + s] = cz;
            out[b * 3072 + s]        = cx;
            out[b * 3072 + 1024 + s] = cy;
            out[b * 3072 + 2048 + s] = cz;
        }

        const unsigned long long c2x = pk2(-cx, -cx);
        const unsigned long long c2y = pk2(-cy, -cy);
        const unsigned long long c2z = pk2(-cz, -cz);

#pragma unroll
        for (int j = 0; j < 4; j++) {
            unsigned long long dx = add2(pxp[j], c2x);
            unsigned long long dy = add2(pyp[j], c2y);
            unsigned long long dz = add2(pzp[j], c2z);
            unsigned long long t  = add2(mul2(dx, dx), mul2(dy, dy));
            unsigned long long d  = add2(t, mul2(dz, dz));
            float d0, d1;
            upk2(d, d0, d1);
            dd[2 * j]     = fminf(dd[2 * j], d0);
            dd[2 * j + 1] = fminf(dd[2 * j + 1], d1);
        }

        float m01 = fmaxf(dd[0], dd[1]), m23 = fmaxf(dd[2], dd[3]);
        float m45 = fmaxf(dd[4], dd[5]), m67 = fmaxf(dd[6], dd[7]);
        float m   = fmaxf(fmaxf(m01, m23), fmaxf(m45, m67));

        unsigned mb  = __float_as_uint(m);
        unsigned whi = __reduce_max_sync(0xffffffffu, mb);
        unsigned idxkey = 0;
        if (mb == whi) {
#pragma unroll
            for (int p = 0; p < 8; p++)
                if (__float_as_uint(dd[p]) == whi) {
                    unsigned k = (unsigned)(8191 - (tid + p * 1024));
                    idxkey = (k > idxkey) ? k : idxkey;
                }
        }
        unsigned wlo = __reduce_max_sync(0xffffffffu, idxkey);
        if (lane == 0)
            wmax[s & 1][warp] = ((unsigned long long)whi << 32) | wlo;
        __syncthreads();

        unsigned long long v = wmax[s & 1][lane];
        unsigned h2 = (unsigned)(v >> 32);
        unsigned l2 = (unsigned)v;
        unsigned fh = __reduce_max_sync(0xffffffffu, h2);
        unsigned fl = __reduce_max_sync(0xffffffffu, (h2 == fh) ? l2 : 0u);
        f = 8191 - (int)fl;
    }
}

// ---------------------------------------------------------------------------
// Kernel 2: KNN (validated numerics, unchanged).
// ---------------------------------------------------------------------------
__global__ void __launch_bounds__(128) knn_kernel()
{
    __shared__ float snx[3072];
    const int b = blockIdx.x >> 3;                    // 16 blocks: 8 per batch
    const int s = (blockIdx.x & 7) * 128 + threadIdx.x;

    for (int t = threadIdx.x; t < 3072; t += 128)
        snx[t] = g_newxyz[b * 3072 + t];
    __syncthreads();

    const float xi = snx[s], yi = snx[1024 + s], zi = snx[2048 + s];
    const float sqi = __fadd_rn(__fadd_rn(__fmul_rn(xi, xi), __fmul_rn(yi, yi)),
                                __fmul_rn(zi, zi));

    float bd[16];
    int   bi[16];
#pragma unroll
    for (int k = 0; k < 16; k++) { bd[k] = 3.4e38f; bi[k] = 0; }

    for (int j = 0; j < NS; j++) {
        float xj = snx[j], yj = snx[1024 + j], zj = snx[2048 + j];
        float sqj = __fadd_rn(__fadd_rn(__fmul_rn(xj, xj), __fmul_rn(yj, yj)),
                              __fmul_rn(zj, zj));
        float dot = __fmaf_rn(zi, zj, __fmaf_rn(yi, yj, __fmul_rn(xi, xj)));
        float d2  = __fsub_rn(__fadd_rn(sqi, sqj), __fmul_rn(2.0f, dot));
        if (d2 < bd[15]) {
            int p = 15;
            while (p > 0 && bd[p - 1] > d2) {
                bd[p] = bd[p - 1];
                bi[p] = bi[p - 1];
                p--;
            }
            bd[p] = d2;
            bi[p] = j;
        }
    }

    const int base = (b * NS + s) * NK;
    for (int k = 0; k < 16; k++) g_knn[base + k] = bi[k];
}

// ---------------------------------------------------------------------------
// Kernel 3: fused conv, two samples per CTA (R13 structure) with ONES
// ELIMINATION: conv0's 128 constant-one input channels are folded into a
// precomputed per-oc bias (g_bias0) that initializes the accumulators.
// conv0 now processes only the 128 real channels (8 chunks x 16 ric).
// x0 shrinks to 8192 floats per team. Everything else identical to R13.
//
// Shared layout (floats):
//   ws 9216 (4608 f32x2 pairs) | team{fg 512, x0 8192, y0 2304, y1 1024,
//   y2 512}=12544 x2  -> total 34304 floats = 137216 B
// ---------------------------------------------------------------------------
#define TEAM_FLOATS 12544
#define SMEM_FLOATS (9216 + 2 * TEAM_FLOATS)

__global__ void __launch_bounds__(384) fused_conv_kernel(
    const float* __restrict__ feats,
    const float* __restrict__ w0, const float* __restrict__ w1,
    const float* __restrict__ w2, const float* __restrict__ w3,
    float* __restrict__ out)
{
    extern __shared__ float sm[];
    float* ws = sm;                                   // 9216 floats (8B aligned)
    unsigned long long* ws2 = reinterpret_cast<unsigned long long*>(ws);

    const int tid  = threadIdx.x;
    const int team = tid / 192;
    const int ttid = tid % 192;

    float* tb = sm + 9216 + team * TEAM_FLOATS;
    float* fg = tb;              // 512
    float* x0 = tb + 512;        // 8192 (128 real channels x 64 px)
    float* y0 = tb + 8704;       // 2304
    float* y1 = y0 + 2304;       // 1024
    float* y2 = y1 + 1024;       // 512

    const int sid = blockIdx.x * 2 + team;
    const int b   = sid >> 10;
    const int s   = sid & 1023;

    // --- Phase A: fg[d][k] (per team) -----------------------------------
    for (int t = ttid; t < 512; t += 192) {
        int d = t >> 4, k = t & 15;
        int j = g_knn[sid * NK + k];
        float v;
        if (d < 3)
            v = g_newxyz[b * 3072 + d * 1024 + j] - g_newxyz[b * 3072 + d * 1024 + s];
        else
            v = feats[(b * NC + (d - 3)) * NPTS + j];
        fg[t] = v;
    }
    __syncthreads();

    // --- Phase B: build squeezed conv0 input, REAL channels only ---------
    // ric in [0,128): q = ric>>5, c = ric&31; global ic = q*64 + c.
    for (int t = ttid; t < 8192; t += 192) {
        int ric = t >> 6, pix = t & 63;
        int y = pix >> 3, x = pix & 7;
        int q = ric >> 5, c = ric & 31;
        int i = 2 * y + (int)(q == 1 || q == 3);
        int j = 2 * x + (int)(q == 1 || q == 2);
        x0[t] = fg[c * 16 + i] * fg[c * 16 + j];
    }

    // --- conv0: 128 real ch 8x8 -> 64ch 6x6 (f32x2, bias-initialized) ----
    const int oy = ttid % 6;
    const int og = ttid / 6;   // 0..31, oc = 2*og, 2*og+1
    unsigned long long acc2[6];
    {
        unsigned long long binit = pk2(g_bias0[2 * og], g_bias0[2 * og + 1]);
#pragma unroll
        for (int i = 0; i < 6; i++) acc2[i] = binit;
    }

    for (int ch = 0; ch < 8; ch++) {            // 8 chunks x 16 real ic
        const int ric0 = ch * 16;
        __syncthreads();                 // protect ws from previous readers
        // stage pairs (k fastest -> coalesced LDG), all 384 threads
        for (int t = tid; t < 4608; t += 384) {
            int k = t % 9, rest = t / 9;
            int ogs = rest % 32, icc = rest / 32;   // icc 0..15
            int ric = ric0 + icc;
            int ic  = (ric >> 5) * 64 + (ric & 31);
            float wa = w0[(2 * ogs)     * 2304 + ic * 9 + k];
            float wb = w0[(2 * ogs + 1) * 2304 + ic * 9 + k];
            ws2[t] = pk2(wa, wb);
        }
        __syncthreads();
        for (int icc = 0; icc < 16; icc++) {
            const float* xs = x0 + ((ric0 + icc) << 6);
            unsigned long long xp[3][8];
#pragma unroll
            for (int r = 0; r < 3; r++) {
                const float4 v0 = *reinterpret_cast<const float4*>(xs + (oy + r) * 8);
                const float4 v1 = *reinterpret_cast<const float4*>(xs + (oy + r) * 8 + 4);
                xp[r][0] = pk2(v0.x, v0.x); xp[r][1] = pk2(v0.y, v0.y);
                xp[r][2] = pk2(v0.z, v0.z); xp[r][3] = pk2(v0.w, v0.w);
                xp[r][4] = pk2(v1.x, v1.x); xp[r][5] = pk2(v1.y, v1.y);
                xp[r][6] = pk2(v1.z, v1.z); xp[r][7] = pk2(v1.w, v1.w);
            }
            const unsigned long long* wp2 = ws2 + (icc * 32 + og) * 9;
#pragma unroll
            for (int ky = 0; ky < 3; ky++)
#pragma unroll
                for (int kx = 0; kx < 3; kx++) {
                    unsigned long long wv = wp2[ky * 3 + kx];
#pragma unroll
                    for (int ox = 0; ox < 6; ox++)
                        acc2[ox] = fma2(wv, xp[ky][ox + kx], acc2[ox]);
                }
        }
    }
    {
        int oc = og * 2;
#pragma unroll
        for (int ox = 0; ox < 6; ox++) {
            float a0, a1;
            upk2(acc2[ox], a0, a1);
            y0[oc * 36 + oy * 6 + ox]       = fmaxf(a0, 0.f);
            y0[(oc + 1) * 36 + oy * 6 + ox] = fmaxf(a1, 0.f);
        }
    }

    // --- conv1: 64ch 6x6 -> 64ch 4x4 (f32x2; R13) ------------------------
    const int oy1 = ttid % 4;
    const int og1 = ttid / 4;  // valid for ttid<128
    unsigned long long bcc[4];
#pragma unroll
    for (int i = 0; i < 4; i++) bcc[i] = 0ull;

    for (int ch = 0; ch < 8; ch++) {
        const int ic0 = ch * 8;
        __syncthreads();
        for (int t = tid; t < 2304; t += 384) {
            int k = t % 9, rest = t / 9;
            int ogs = rest % 32, icc = rest / 32;
            int ic  = ic0 + icc;
            float wa = w1[(2 * ogs)     * 576 + ic * 9 + k];
            float wb = w1[(2 * ogs + 1) * 576 + ic * 9 + k];
            ws2[t] = pk2(wa, wb);
        }
        __syncthreads();
        if (ttid < 128) {
            for (int icc = 0; icc < 8; icc++) {
                const float* xs = y0 + (ic0 + icc) * 36;
                unsigned long long xp[3][6];
#pragma unroll
                for (int r = 0; r < 3; r++) {
                    const float2 v0 = *reinterpret_cast<const float2*>(xs + (oy1 + r) * 6);
                    const float2 v1 = *reinterpret_cast<const float2*>(xs + (oy1 + r) * 6 + 2);
                    const float2 v2 = *reinterpret_cast<const float2*>(xs + (oy1 + r) * 6 + 4);
                    xp[r][0] = pk2(v0.x, v0.x); xp[r][1] = pk2(v0.y, v0.y);
                    xp[r][2] = pk2(v1.x, v1.x); xp[r][3] = pk2(v1.y, v1.y);
                    xp[r][4] = pk2(v2.x, v2.x); xp[r][5] = pk2(v2.y, v2.y);
                }
                const unsigned long long* wp2 = ws2 + (icc * 32 + og1) * 9;
#pragma unroll
                for (int ky = 0; ky < 3; ky++)
#pragma unroll
                    for (int kx = 0; kx < 3; kx++) {
                        unsigned long long wv = wp2[ky * 3 + kx];
#pragma unroll
                        for (int ox = 0; ox < 4; ox++)
                            bcc[ox] = fma2(wv, xp[ky][ox + kx], bcc[ox]);
                    }
            }
        }
    }
    if (ttid < 128) {
        int oc = og1 * 2;
#pragma unroll
        for (int ox = 0; ox < 4; ox++) {
            float b0, b1;
            upk2(bcc[ox], b0, b1);
            y1[oc * 16 + oy1 * 4 + ox]       = fmaxf(b0, 0.f);
            y1[(oc + 1) * 16 + oy1 * 4 + ox] = fmaxf(b1, 0.f);
        }
    }

    // --- conv2: 64ch 4x4 -> 128ch 2x2 (scalar; R13) ----------------------
    float c2[4] = {0.f, 0.f, 0.f, 0.f};
    for (int ch = 0; ch < 16; ch++) {
        const int ic0 = ch * 4;
        __syncthreads();
        for (int t = tid; t < 4608; t += 384) {
            int icc = t / 1152, rem = t % 1152;
            int oc = rem / 9, k = rem % 9;
            ws[t] = w2[oc * 576 + (ic0 + icc) * 9 + k];
        }
        __syncthreads();
        if (ttid < 128) {
            for (int icc = 0; icc < 4; icc++) {
                const float* xs = y1 + (ic0 + icc) * 16;
                float xr[16];
#pragma unroll
                for (int p = 0; p < 4; p++) {
                    const float4 v = *reinterpret_cast<const float4*>(xs + p * 4);
                    xr[p * 4 + 0] = v.x; xr[p * 4 + 1] = v.y;
                    xr[p * 4 + 2] = v.z; xr[p * 4 + 3] = v.w;
                }
                const float* wp = ws + icc * 1152 + ttid * 9;
#pragma unroll
                for (int ky = 0; ky < 3; ky++)
#pragma unroll
                    for (int kx = 0; kx < 3; kx++) {
                        float wv = wp[ky * 3 + kx];
#pragma unroll
                        for (int oy2 = 0; oy2 < 2; oy2++)
#pragma unroll
                            for (int ox2 = 0; ox2 < 2; ox2++)
                                c2[oy2 * 2 + ox2] += xr[(oy2 + ky) * 4 + ox2 + kx] * wv;
                    }
            }
        }
    }
    if (ttid < 128) {
#pragma unroll
        for (int p = 0; p < 4; p++) y2[ttid * 4 + p] = fmaxf(c2[p], 0.f);
    }

    // --- conv3: 128ch 2x2 -> 128ch 1x1 (scalar; R13) ---------------------
    float acc3 = 0.f;
    for (int ch = 0; ch < 16; ch++) {
        const int ic0 = ch * 8;
        __syncthreads();
        for (int t = tid; t < 4096; t += 384) {
            int icc = t >> 9, rem = t & 511;
            int oc = rem >> 2, k = rem & 3;
            ws[t] = w3[oc * 512 + (ic0 + icc) * 4 + k];
        }
        __syncthreads();
        if (ttid < 128) {
            for (int icc = 0; icc < 8; icc++) {
                const float* xs = y2 + (ic0 + icc) * 4;
                const float* wp = ws + icc * 512 + ttid * 4;
                acc3 += xs[0] * wp[0] + xs[1] * wp[1] + xs[2] * wp[2] + xs[3] * wp[3];
            }
        }
    }
    if (ttid < 128) {
        out[OUT_NP + b * 131072 + ttid * 1024 + s] = fmaxf(acc3, 0.f);
    }
}

// ---------------------------------------------------------------------------
extern "C" void kernel_launch(void* const* d_in, const int* in_sizes, int n_in,
                              void* d_out, int out_size)
{
    const float* xyz   = (const float*)d_in[0];
    const float* feats = (const float*)d_in[1];
    const float* w0    = (const float*)d_in[2];
    const float* w1    = (const float*)d_in[3];
    const float* w2    = (const float*)d_in[4];
    const float* w3    = (const float*)d_in[5];
    float* out = (float*)d_out;

    cudaFuncSetAttribute(fused_conv_kernel,
                         cudaFuncAttributeMaxDynamicSharedMemorySize,
                         SMEM_FLOATS * (int)sizeof(float));

    bias0_kernel<<<1, 64>>>(w0);
    fps_kernel<<<NB, 1024>>>(xyz, out);
    knn_kernel<<<16, 128>>>();
    fused_conv_kernel<<<NB * NS / 2, 384, SMEM_FLOATS * sizeof(float)>>>(
        feats, w0, w1, w2, w3, out);
}

// round 16
// speedup vs baseline: 2.0314x; 1.0434x over previous
#include <cuda_runtime.h>
#include <cuda_bf16.h>

// Problem constants
#define NB   2
#define NPTS 8192
#define NS   1024
#define NK   16
#define NC   29

// Output layout (concatenated flattened reference returns, float32):
// new_xyz  (2,3,1024)    -> [0, 6144)
// new_points (2,128,1024)-> [6144, 268288)
// fps_idx  (2,1024)      -> [268288, 270336)
#define OUT_NP  6144
#define OUT_FPS 268288

// Scratch (static device globals; no allocation allowed)
__device__ int   g_fps[NB * NS];
__device__ float g_newxyz[NB * 3 * NS];
__device__ int   g_knn[NB * NS * NK];
__device__ float g_bias0[64];   // conv0 ones-channel contribution per oc

// ---- packed f32x2 helpers (Blackwell; PTX-only, per-lane IEEE fp32) ----
__device__ __forceinline__ unsigned long long pk2(float lo, float hi)
{
    unsigned long long r;
    asm("mov.b64 %0, {%1,%2};" : "=l"(r) : "f"(lo), "f"(hi));
    return r;
}
__device__ __forceinline__ unsigned long long fma2(unsigned long long a,
                                                   unsigned long long b,
                                                   unsigned long long c)
{
    unsigned long long d;
    asm("fma.rn.f32x2 %0, %1, %2, %3;" : "=l"(d) : "l"(a), "l"(b), "l"(c));
    return d;
}
__device__ __forceinline__ unsigned long long add2(unsigned long long a,
                                                   unsigned long long b)
{
    unsigned long long d;
    asm("add.rn.f32x2 %0, %1, %2;" : "=l"(d) : "l"(a), "l"(b));
    return d;
}
__device__ __forceinline__ unsigned long long mul2(unsigned long long a,
                                                   unsigned long long b)
{
    unsigned long long d;
    asm("mul.rn.f32x2 %0, %1, %2;" : "=l"(d) : "l"(a), "l"(b));
    return d;
}
__device__ __forceinline__ void upk2(unsigned long long v, float& lo, float& hi)
{
    asm("mov.b64 {%0,%1}, %2;" : "=f"(lo), "=f"(hi) : "l"(v));
}

// ---------------------------------------------------------------------------
// Kernel 0: precompute conv0 ones-channel bias (input-independent).
// ---------------------------------------------------------------------------
__global__ void bias0_kernel(const float* __restrict__ w0)
{
    int oc = threadIdx.x;       // 64 threads
    float s = 0.f;
    for (int q = 0; q < 4; q++)
        for (int c = 32; c < 64; c++) {
            const float* p = w0 + oc * 2304 + (q * 64 + c) * 9;
#pragma unroll
            for (int k = 0; k < 9; k++) s += p[k];
        }
    g_bias0[oc] = s;
}

// ---------------------------------------------------------------------------
// Kernel 1: FPS (R12/R13 version, measured 626us). Unchanged.
// ---------------------------------------------------------------------------
__global__ void __launch_bounds__(1024) fps_kernel(const float* __restrict__ xyz,
                                                   float* __restrict__ out)
{
    const int b    = blockIdx.x;
    const int tid  = threadIdx.x;
    const int lane = tid & 31;
    const int warp = tid >> 5;
    const float* X = xyz + b * 3 * NPTS;

    unsigned long long pxp[4], pyp[4], pzp[4];
    float dd[8];
#pragma unroll
    for (int j = 0; j < 4; j++) {
        int n0 = tid + (2 * j) * 1024;
        int n1 = tid + (2 * j + 1) * 1024;
        pxp[j] = pk2(X[n0], X[n1]);
        pyp[j] = pk2(X[NPTS + n0], X[NPTS + n1]);
        pzp[j] = pk2(X[2 * NPTS + n0], X[2 * NPTS + n1]);
        dd[2 * j] = 1e10f; dd[2 * j + 1] = 1e10f;
    }

    __shared__ unsigned long long wmax[2][32];

    int f = 0;
    for (int s = 0; s < NS; s++) {
        float cx = X[f];
        float cy = X[NPTS + f];
        float cz = X[2 * NPTS + f];

        if (tid == 0) {
            g_fps[b * NS + s] = f;
            out[OUT_FPS + b * NS + s] = (float)f;
            g_newxyz[b * 3072 + s]        = cx;
            g_newxyz[b * 3072 + 1024 + s] = cy;
            g_newxyz[b * 3072 + 2048 + s] = cz;
            out[b * 3072 + s]        = cx;
            out[b * 3072 + 1024 + s] = cy;
            out[b * 3072 + 2048 + s] = cz;
        }

        const unsigned long long c2x = pk2(-cx, -cx);
        const unsigned long long c2y = pk2(-cy, -cy);
        const unsigned long long c2z = pk2(-cz, -cz);

#pragma unroll
        for (int j = 0; j < 4; j++) {
            unsigned long long dx = add2(pxp[j], c2x);
            unsigned long long dy = add2(pyp[j], c2y);
            unsigned long long dz = add2(pzp[j], c2z);
            unsigned long long t  = add2(mul2(dx, dx), mul2(dy, dy));
            unsigned long long d  = add2(t, mul2(dz, dz));
            float d0, d1;
            upk2(d, d0, d1);
            dd[2 * j]     = fminf(dd[2 * j], d0);
            dd[2 * j + 1] = fminf(dd[2 * j + 1], d1);
        }

        float m01 = fmaxf(dd[0], dd[1]), m23 = fmaxf(dd[2], dd[3]);
        float m45 = fmaxf(dd[4], dd[5]), m67 = fmaxf(dd[6], dd[7]);
        float m   = fmaxf(fmaxf(m01, m23), fmaxf(m45, m67));

        unsigned mb  = __float_as_uint(m);
        unsigned whi = __reduce_max_sync(0xffffffffu, mb);
        unsigned idxkey = 0;
        if (mb == whi) {
#pragma unroll
            for (int p = 0; p < 8; p++)
                if (__float_as_uint(dd[p]) == whi) {
                    unsigned k = (unsigned)(8191 - (tid + p * 1024));
                    idxkey = (k > idxkey) ? k : idxkey;
                }
        }
        unsigned wlo = __reduce_max_sync(0xffffffffu, idxkey);
        if (lane == 0)
            wmax[s & 1][warp] = ((unsigned long long)whi << 32) | wlo;
        __syncthreads();

        unsigned long long v = wmax[s & 1][lane];
        unsigned h2 = (unsigned)(v >> 32);
        unsigned l2 = (unsigned)v;
        unsigned fh = __reduce_max_sync(0xffffffffu, h2);
        unsigned fl = __reduce_max_sync(0xffffffffu, (h2 == fh) ? l2 : 0u);
        f = 8191 - (int)fl;
    }
}

// ---------------------------------------------------------------------------
// Kernel 2: KNN. Same validated numerics; ssq precomputed once in shared
// (identical fp32 instructions per value -> bit-identical d2), inner loop
// unrolled for ILP.
// ---------------------------------------------------------------------------
__global__ void __launch_bounds__(128) knn_kernel()
{
    __shared__ float snx[3072];
    __shared__ float ssq[1024];
    const int b = blockIdx.x >> 3;                    // 16 blocks: 8 per batch
    const int s = (blockIdx.x & 7) * 128 + threadIdx.x;

    for (int t = threadIdx.x; t < 3072; t += 128)
        snx[t] = g_newxyz[b * 3072 + t];
    __syncthreads();
    for (int t = threadIdx.x; t < 1024; t += 128) {
        float x = snx[t], y = snx[1024 + t], z = snx[2048 + t];
        ssq[t] = __fadd_rn(__fadd_rn(__fmul_rn(x, x), __fmul_rn(y, y)),
                           __fmul_rn(z, z));
    }
    __syncthreads();

    const float xi = snx[s], yi = snx[1024 + s], zi = snx[2048 + s];
    const float sqi = ssq[s];

    float bd[16];
    int   bi[16];
#pragma unroll
    for (int k = 0; k < 16; k++) { bd[k] = 3.4e38f; bi[k] = 0; }

#pragma unroll 4
    for (int j = 0; j < NS; j++) {
        float xj = snx[j], yj = snx[1024 + j], zj = snx[2048 + j];
        float dot = __fmaf_rn(zi, zj, __fmaf_rn(yi, yj, __fmul_rn(xi, xj)));
        float d2  = __fsub_rn(__fadd_rn(sqi, ssq[j]), __fmul_rn(2.0f, dot));
        if (d2 < bd[15]) {
            int p = 15;
            while (p > 0 && bd[p - 1] > d2) {
                bd[p] = bd[p - 1];
                bi[p] = bi[p - 1];
                p--;
            }
            bd[p] = d2;
            bi[p] = j;
        }
    }

    const int base = (b * NS + s) * NK;
    for (int k = 0; k < 16; k++) g_knn[base + k] = bi[k];
}

// ---------------------------------------------------------------------------
// Kernel 3: fused conv, two samples per CTA, ones-eliminated conv0.
// NEW vs R14: conv0/conv1 compute mapping og=LANE, oy=WARP ->
//   * activation row loads are warp-uniform -> LDS broadcast (1 wavefront
//     instead of 4 per LDS.128) — removes the dominant L1 wavefront load
//   * weights staged into padded transposed layout ws2[icc*297 + k*33 + og]
//     -> compute reads lane-stride-1 (conflict-free); the staging LDG
//     enumeration KEEPS k fastest (R13-proven coalescing; R12's regression
//     came from changing the LDG order, which stays untouched here).
// Arithmetic order identical -> bit-exact vs R14.
//
// Shared layout (floats):
//   ws 9504 (16*297 u64) | team{fg 512, x0 8192, y0 2304, y1 1024, y2 512}
//   = 12544 x2  -> total 34592 floats = 138368 B
// ---------------------------------------------------------------------------
#define WS_FLOATS  9504
#define TEAM_FLOATS 12544
#define SMEM_FLOATS (WS_FLOATS + 2 * TEAM_FLOATS)

__global__ void __launch_bounds__(384) fused_conv_kernel(
    const float* __restrict__ feats,
    const float* __restrict__ w0, const float* __restrict__ w1,
    const float* __restrict__ w2, const float* __restrict__ w3,
    float* __restrict__ out)
{
    extern __shared__ float sm[];
    float* ws = sm;                                   // WS_FLOATS (8B aligned)
    unsigned long long* ws2 = reinterpret_cast<unsigned long long*>(ws);

    const int tid  = threadIdx.x;
    const int team = tid / 192;
    const int ttid = tid % 192;

    float* tb = sm + WS_FLOATS + team * TEAM_FLOATS;
    float* fg = tb;              // 512
    float* x0 = tb + 512;        // 8192 (128 real channels x 64 px)
    float* y0 = tb + 8704;       // 2304
    float* y1 = y0 + 2304;       // 1024
    float* y2 = y1 + 1024;       // 512

    const int sid = blockIdx.x * 2 + team;
    const int b   = sid >> 10;
    const int s   = sid & 1023;

    // --- Phase A: fg[d][k] (per team) -----------------------------------
    for (int t = ttid; t < 512; t += 192) {
        int d = t >> 4, k = t & 15;
        int j = g_knn[sid * NK + k];
        float v;
        if (d < 3)
            v = g_newxyz[b * 3072 + d * 1024 + j] - g_newxyz[b * 3072 + d * 1024 + s];
        else
            v = feats[(b * NC + (d - 3)) * NPTS + j];
        fg[t] = v;
    }
    __syncthreads();

    // --- Phase B: build squeezed conv0 input, REAL channels only ---------
    for (int t = ttid; t < 8192; t += 192) {
        int ric = t >> 6, pix = t & 63;
        int y = pix >> 3, x = pix & 7;
        int q = ric >> 5, c = ric & 31;
        int i = 2 * y + (int)(q == 1 || q == 3);
        int j = 2 * x + (int)(q == 1 || q == 2);
        x0[t] = fg[c * 16 + i] * fg[c * 16 + j];
    }

    // --- conv0: 128 real ch 8x8 -> 64ch 6x6 (f32x2, bias-init) -----------
    const int og = ttid & 31;   // LANE: oc pair 2og, 2og+1
    const int oy = ttid >> 5;   // WARP: output row 0..5
    unsigned long long acc2[6];
    {
        unsigned long long binit = pk2(g_bias0[2 * og], g_bias0[2 * og + 1]);
#pragma unroll
        for (int i = 0; i < 6; i++) acc2[i] = binit;
    }

    for (int ch = 0; ch < 8; ch++) {            // 8 chunks x 16 real ic
        const int ric0 = ch * 16;
        __syncthreads();                 // protect ws from previous readers
        // LDG enumeration: k fastest (coalesced, R13-proven). Write into
        // padded transposed layout for lane-stride-1 compute reads.
        for (int t = tid; t < 4608; t += 384) {
            int k = t % 9, rest = t / 9;
            int ogs = rest % 32, icc = rest / 32;   // icc 0..15
            int ric = ric0 + icc;
            int ic  = (ric >> 5) * 64 + (ric & 31);
            float wa = w0[(2 * ogs)     * 2304 + ic * 9 + k];
            float wb = w0[(2 * ogs + 1) * 2304 + ic * 9 + k];
            ws2[icc * 297 + k * 33 + ogs] = pk2(wa, wb);
        }
        __syncthreads();
        for (int icc = 0; icc < 16; icc++) {
            const float* xs = x0 + ((ric0 + icc) << 6);
            unsigned long long xp[3][8];
#pragma unroll
            for (int r = 0; r < 3; r++) {   // warp-uniform address -> broadcast
                const float4 v0 = *reinterpret_cast<const float4*>(xs + (oy + r) * 8);
                const float4 v1 = *reinterpret_cast<const float4*>(xs + (oy + r) * 8 + 4);
                xp[r][0] = pk2(v0.x, v0.x); xp[r][1] = pk2(v0.y, v0.y);
                xp[r][2] = pk2(v0.z, v0.z); xp[r][3] = pk2(v0.w, v0.w);
                xp[r][4] = pk2(v1.x, v1.x); xp[r][5] = pk2(v1.y, v1.y);
                xp[r][6] = pk2(v1.z, v1.z); xp[r][7] = pk2(v1.w, v1.w);
            }
            const unsigned long long* wp2 = ws2 + icc * 297 + og;
#pragma unroll
            for (int ky = 0; ky < 3; ky++)
#pragma unroll
                for (int kx = 0; kx < 3; kx++) {
                    unsigned long long wv = wp2[(ky * 3 + kx) * 33];  // lane-stride-1
#pragma unroll
                    for (int ox = 0; ox < 6; ox++)
                        acc2[ox] = fma2(wv, xp[ky][ox + kx], acc2[ox]);
                }
        }
    }
    {
        int oc = og * 2;
#pragma unroll
        for (int ox = 0; ox < 6; ox++) {
            float a0, a1;
            upk2(acc2[ox], a0, a1);
            y0[oc * 36 + oy * 6 + ox]       = fmaxf(a0, 0.f);
            y0[(oc + 1) * 36 + oy * 6 + ox] = fmaxf(a1, 0.f);
        }
    }

    // --- conv1: 64ch 6x6 -> 64ch 4x4 (f32x2; og=lane, oy=warp) -----------
    const int og1 = ttid & 31;
    const int oy1 = ttid >> 5;  // warps 0..3 active (ttid < 128)
    unsigned long long bcc[4];
#pragma unroll
    for (int i = 0; i < 4; i++) bcc[i] = 0ull;

    for (int ch = 0; ch < 8; ch++) {
        const int ic0 = ch * 8;
        __syncthreads();
        for (int t = tid; t < 2304; t += 384) {
            int k = t % 9, rest = t / 9;
            int ogs = rest % 32, icc = rest / 32;   // icc 0..7
            int ic  = ic0 + icc;
            float wa = w1[(2 * ogs)     * 576 + ic * 9 + k];
            float wb = w1[(2 * ogs + 1) * 576 + ic * 9 + k];
            ws2[icc * 297 + k * 33 + ogs] = pk2(wa, wb);
        }
        __syncthreads();
        if (ttid < 128) {
            for (int icc = 0; icc < 8; icc++) {
                const float* xs = y0 + (ic0 + icc) * 36;
                unsigned long long xp[3][6];
#pragma unroll
                for (int r = 0; r < 3; r++) {   // warp-uniform -> broadcast
                    const float2 v0 = *reinterpret_cast<const float2*>(xs + (oy1 + r) * 6);
                    const float2 v1 = *reinterpret_cast<const float2*>(xs + (oy1 + r) * 6 + 2);
                    const float2 v2 = *reinterpret_cast<const float2*>(xs + (oy1 + r) * 6 + 4);
                    xp[r][0] = pk2(v0.x, v0.x); xp[r][1] = pk2(v0.y, v0.y);
                    xp[r][2] = pk2(v1.x, v1.x); xp[r][3] = pk2(v1.y, v1.y);
                    xp[r][4] = pk2(v2.x, v2.x); xp[r][5] = pk2(v2.y, v2.y);
                }
                const unsigned long long* wp2 = ws2 + icc * 297 + og1;
#pragma unroll
                for (int ky = 0; ky < 3; ky++)
#pragma unroll
                    for (int kx = 0; kx < 3; kx++) {
                        unsigned long long wv = wp2[(ky * 3 + kx) * 33];
#pragma unroll
                        for (int ox = 0; ox < 4; ox++)
                            bcc[ox] = fma2(wv, xp[ky][ox + kx], bcc[ox]);
                    }
            }
        }
    }
    if (ttid < 128) {
        int oc = og1 * 2;
#pragma unroll
        for (int ox = 0; ox < 4; ox++) {
            float b0, b1;
            upk2(bcc[ox], b0, b1);
            y1[oc * 16 + oy1 * 4 + ox]       = fmaxf(b0, 0.f);
            y1[(oc + 1) * 16 + oy1 * 4 + ox] = fmaxf(b1, 0.f);
        }
    }

    // --- conv2: 64ch 4x4 -> 128ch 2x2 (scalar; R13, conflict-free) -------
    float c2[4] = {0.f, 0.f, 0.f, 0.f};
    for (int ch = 0; ch < 16; ch++) {
        const int ic0 = ch * 4;
        __syncthreads();
        for (int t = tid; t < 4608; t += 384) {
            int icc = t / 1152, rem = t % 1152;
            int oc = rem / 9, k = rem % 9;
            ws[t] = w2[oc * 576 + (ic0 + icc) * 9 + k];
        }
        __syncthreads();
        if (ttid < 128) {
            for (int icc = 0; icc < 4; icc++) {
                const float* xs = y1 + (ic0 + icc) * 16;
                float xr[16];
#pragma unroll
                for (int p = 0; p < 4; p++) {
                    const float4 v = *reinterpret_cast<const float4*>(xs + p * 4);
                    xr[p * 4 + 0] = v.x; xr[p * 4 + 1] = v.y;
                    xr[p * 4 + 2] = v.z; xr[p * 4 + 3] = v.w;
                }
                const float* wp = ws + icc * 1152 + ttid * 9;
#pragma unroll
                for (int ky = 0; ky < 3; ky++)
#pragma unroll
                    for (int kx = 0; kx < 3; kx++) {
                        float wv = wp[ky * 3 + kx];
#pragma unroll
                        for (int oy2 = 0; oy2 < 2; oy2++)
#pragma unroll
                            for (int ox2 = 0; ox2 < 2; ox2++)
                                c2[oy2 * 2 + ox2] += xr[(oy2 + ky) * 4 + ox2 + kx] * wv;
                    }
            }
        }
    }
    if (ttid < 128) {
#pragma unroll
        for (int p = 0; p < 4; p++) y2[ttid * 4 + p] = fmaxf(c2[p], 0.f);
    }

    // --- conv3: 128ch 2x2 -> 128ch 1x1 (scalar; R13) ---------------------
    float acc3 = 0.f;
    for (int ch = 0; ch < 16; ch++) {
        const int ic0 = ch * 8;
        __syncthreads();
        for (int t = tid; t < 4096; t += 384) {
            int icc = t >> 9, rem = t & 511;
            int oc = rem >> 2, k = rem & 3;
            ws[t] = w3[oc * 512 + (ic0 + icc) * 4 + k];
        }
        __syncthreads();
        if (ttid < 128) {
            for (int icc = 0; icc < 8; icc++) {
                const float* xs = y2 + (ic0 + icc) * 4;
                const float* wp = ws + icc * 512 + ttid * 4;
                acc3 += xs[0] * wp[0] + xs[1] * wp[1] + xs[2] * wp[2] + xs[3] * wp[3];
            }
        }
    }
    if (ttid < 128) {
        out[OUT_NP + b * 131072 + ttid * 1024 + s] = fmaxf(acc3, 0.f);
    }
}

// ---------------------------------------------------------------------------
extern "C" void kernel_launch(void* const* d_in, const int* in_sizes, int n_in,
                              void* d_out, int out_size)
{
    const float* xyz   = (const float*)d_in[0];
    const float* feats = (const float*)d_in[1];
    const float* w0    = (const float*)d_in[2];
    const float* w1    = (const float*)d_in[3];
    const float* w2    = (const float*)d_in[4];
    const float* w3    = (const float*)d_in[5];
    float* out = (float*)d_out;

    cudaFuncSetAttribute(fused_conv_kernel,
                         cudaFuncAttributeMaxDynamicSharedMemorySize,
                         SMEM_FLOATS * (int)sizeof(float));

    bias0_kernel<<<1, 64>>>(w0);
    fps_kernel<<<NB, 1024>>>(xyz, out);
    knn_kernel<<<16, 128>>>();
    fused_conv_kernel<<<NB * NS / 2, 384, SMEM_FLOATS * sizeof(float)>>>(
        feats, w0, w1, w2, w3, out);
}